// round 11
// baseline (speedup 1.0000x reference)
#include <cuda_runtime.h>
#include <cuda_fp16.h>
#include <cstdint>

// SynergyGraph: out[b,s,t] = (W[seq[b,s]] . W[seq[b,t]]) / sqrt(64)
// B=16, S=2048, D=64, VOCAB=32000. Output fp32 [16,2048,2048].
//
// fp16 single-pass mma.sync m16n8k16, fp32 accum (rel err ~3e-4).
// Lower-triangle tiles only (Gram symmetry); mirror via SMEM transpose.
// 128x64 CTA tile, 32x32 warp tiles, 64 regs -> 4 CTAs/SM.
//
// R11: direct-tile STG.64 from fragments spread 8 rows/instr = 8 L1 wf each
// (~1024 wf/CTA, largest L1 consumer). Stage the direct tile through SMEM
// (row-major, stride 68 floats, <=2-way STS conflict) and drain with
// coalesced STG.128 like the mirror path: ~-13% L1 traffic.

#define DEVFN __device__ __forceinline__

static constexpr int BATCH  = 16;
static constexpr int SEQ    = 2048;
static constexpr int TILE   = 128;
static constexpr int NT     = SEQ / TILE;            // 16
static constexpr int NPAIRS = NT * (NT + 1) / 2;     // 136

static constexpr int ROW_BYTES = 144;                // 64 fp16 padded to 72
static constexpr int A_BYTES = 128 * ROW_BYTES;      // 18432
static constexpr int OFF_A = 0;
static constexpr int OFF_B = A_BYTES;
// staging buffers (sequential reuse of one allocation):
//   transpose: 64 cols x 128 rows fp32, stride LDT=132  (33792 B)
//   direct:    128 rows x 64 cols fp32, stride RSD=68   (34816 B)
static constexpr int LDT = 132;
static constexpr int RSD = 68;
static constexpr int SMEM_BYTES = 128 * RSD * 4;     // 34816

DEVFN uint32_t smem_u32(const void* p) {
    uint32_t a;
    asm("{ .reg .u64 t; cvta.to.shared.u64 t, %1; cvt.u32.u64 %0, t; }"
        : "=r"(a) : "l"(p));
    return a;
}

DEVFN void sts64(uint32_t addr, uint32_t a, uint32_t b) {
    asm volatile("st.shared.v2.b32 [%0], {%1, %2};"
                 :: "r"(addr), "r"(a), "r"(b) : "memory");
}

DEVFN void ldsm4(uint32_t* r, uint32_t addr) {
    asm volatile("ldmatrix.sync.aligned.m8n8.x4.shared.b16 {%0, %1, %2, %3}, [%4];"
                 : "=r"(r[0]), "=r"(r[1]), "=r"(r[2]), "=r"(r[3]) : "r"(addr));
}

DEVFN void mma16816(float* c, const uint32_t* a, uint32_t b0, uint32_t b1) {
    asm volatile(
        "mma.sync.aligned.m16n8k16.row.col.f32.f16.f16.f32 "
        "{%0, %1, %2, %3}, {%4, %5, %6, %7}, {%8, %9}, {%0, %1, %2, %3};"
        : "+f"(c[0]), "+f"(c[1]), "+f"(c[2]), "+f"(c[3])
        : "r"(a[0]), "r"(a[1]), "r"(a[2]), "r"(a[3]), "r"(b0), "r"(b1));
}

__global__ void __launch_bounds__(256, 4)
synergy_kernel(const int* __restrict__ seq,
               const float* __restrict__ weight,
               float* __restrict__ out)
{
    extern __shared__ char smem_raw[];
    const uint32_t smem = smem_u32(smem_raw);
    float* smem_f = reinterpret_cast<float*>(smem_raw);

    const int tid  = threadIdx.x;
    const int wid  = tid >> 5;
    const int lane = tid & 31;

    // ---- pair decode: p -> (mT, nT), mT >= nT; half picks 64-col slice ----
    const int p    = blockIdx.x;
    const int half = blockIdx.y;
    const int bb   = blockIdx.z;
    int mT = (int)((sqrtf(8.0f * (float)p + 1.0f) - 1.0f) * 0.5f);
    while ((mT + 1) * (mT + 2) / 2 <= p) ++mT;
    while (mT * (mT + 1) / 2 > p) --mT;
    const int nT = p - mT * (mT + 1) / 2;
    const int ncol0 = nT * TILE + half * 64;   // output col base of this CTA
    const bool diag = (mT == nT);

    // ---- Coalesced gather + fp16 convert ----
    // iters 0..7: A rows (128). iters 8..11: B rows (64) — skipped when diag
    // (B rows alias rows half*64..half*64+63 of the A tile).
    {
        const int chunk = tid & 15;          // 16B chunk of the fp32 row
        const int rsub  = tid >> 4;
        const int seq_base = bb * SEQ;
        const int nIter = diag ? 8 : 12;

        #pragma unroll
        for (int g0 = 0; g0 < 12; g0 += 6) {     // two groups of 6
            if (g0 >= nIter) break;
            int idxv[6];
            #pragma unroll
            for (int j = 0; j < 6; ++j) {        // batch seq-index loads (MLP)
                const int iter = g0 + j;
                if (iter >= nIter) break;
                const int row192 = iter * 16 + rsub;
                const bool isA   = (row192 < 128);
                const int  pos   = isA ? (mT * TILE + row192)
                                       : (ncol0 + row192 - 128);
                idxv[j] = seq[seq_base + pos];
            }
            #pragma unroll
            for (int j = 0; j < 6; ++j) {        // independent weight loads
                const int iter = g0 + j;
                if (iter >= nIter) break;
                const int row192 = iter * 16 + rsub;
                const bool isA   = (row192 < 128);
                const int  row   = isA ? row192 : (row192 - 128);

                const float4 v =
                    reinterpret_cast<const float4*>(weight)[(size_t)idxv[j] * 16 + chunk];
                const __half2 h0 = __floats2half2_rn(v.x, v.y);
                const __half2 h1 = __floats2half2_rn(v.z, v.w);

                const uint32_t base = smem + (isA ? OFF_A : OFF_B)
                                    + (uint32_t)row * ROW_BYTES + (uint32_t)chunk * 8;
                sts64(base, *reinterpret_cast<const uint32_t*>(&h0),
                            *reinterpret_cast<const uint32_t*>(&h1));
            }
        }
    }
    __syncthreads();

    // ---- Warp tiling: 8 warps = 4 (M) x 2 (N); warp tile 32x32 ----
    const int wm = (wid >> 1) * 32;   // 0,32,64,96
    const int wn = (wid & 1) * 32;    // 0,32

    float acc[2][4][4];
    #pragma unroll
    for (int mi = 0; mi < 2; ++mi)
        #pragma unroll
        for (int nj = 0; nj < 4; ++nj)
            #pragma unroll
            for (int q = 0; q < 4; ++q) acc[mi][nj][q] = 0.f;

    const int a_row  = lane & 15;
    const int a_col  = (lane >> 4) * 8;
    const int b_row  = (lane & 7) + ((lane >> 4) * 8);
    const int b_col  = ((lane >> 3) & 1) * 8;

    const uint32_t a_base =
        smem + OFF_A + (uint32_t)(wm + a_row) * ROW_BYTES + (uint32_t)a_col * 2;
    // diagonal: B tile aliases rows half*64.. of the A tile
    const uint32_t b_tile = diag ? (smem + OFF_A + (uint32_t)(half * 64) * ROW_BYTES)
                                 : (smem + OFF_B);
    const uint32_t b_base =
        b_tile + (uint32_t)(wn + b_row) * ROW_BYTES + (uint32_t)b_col * 2;

    #pragma unroll
    for (int k = 0; k < 4; ++k) {           // k16 steps over K=64
        const uint32_t koff = (uint32_t)(k * 16) * 2;

        uint32_t bf[2][4];
        #pragma unroll
        for (int bj = 0; bj < 2; ++bj)
            ldsm4(bf[bj], b_base + koff + (uint32_t)(bj * 16) * ROW_BYTES);

        #pragma unroll
        for (int mi = 0; mi < 2; ++mi) {
            uint32_t af[4];
            ldsm4(af, a_base + koff + (uint32_t)(mi * 16) * ROW_BYTES);

            #pragma unroll
            for (int nj = 0; nj < 4; ++nj) {
                const uint32_t* bp = &bf[nj >> 1][(nj & 1) * 2];
                mma16816(acc[mi][nj], af, bp[0], bp[1]);
            }
        }
    }

    const int g = lane >> 2;     // row within 8
    const int t = lane & 3;      // col pair

    __syncthreads();   // all ldsm reads of gather smem complete; buffer reusable

    // ---- Off-diagonal: transpose-stage then drain mirror tile ----
    if (!diag) {
        // smem_t[c][r]: bank = (4c + r) mod 32 = 8t + g + const -> conflict-free
        #pragma unroll
        for (int mi = 0; mi < 2; ++mi) {
            #pragma unroll
            for (int nj = 0; nj < 4; ++nj) {
                #pragma unroll
                for (int h = 0; h < 2; ++h) {
                    const int row = wm + mi * 16 + 8 * h + g;
                    const int c0  = wn + nj * 8 + 2 * t;
                    smem_f[(c0 + 0) * LDT + row] = acc[mi][nj][2 * h + 0] * 0.125f;
                    smem_f[(c0 + 1) * LDT + row] = acc[mi][nj][2 * h + 1] * 0.125f;
                }
            }
        }
        __syncthreads();
        // mirror: out[b, ncol0+c, mT*128+r], coalesced float4 rows
        float* obase = out + ((size_t)bb * SEQ + (size_t)ncol0) * SEQ
                           + (size_t)(mT * TILE);
        #pragma unroll
        for (int i = 0; i < 8; ++i) {
            const int id = i * 256 + tid;
            const int r  = id >> 5;          // 0..63
            const int c4 = id & 31;
            const float4 v = *reinterpret_cast<const float4*>(smem_f + r * LDT + c4 * 4);
            __stcs(reinterpret_cast<float4*>(obase + (size_t)r * SEQ + c4 * 4), v);
        }
        __syncthreads();   // mirror LDS complete; buffer reusable
    }

    // ---- Stage direct tile row-major (stride RSD=68, <=2-way STS conflict) ----
    #pragma unroll
    for (int mi = 0; mi < 2; ++mi) {
        #pragma unroll
        for (int nj = 0; nj < 4; ++nj) {
            #pragma unroll
            for (int h = 0; h < 2; ++h) {
                const int row = wm + mi * 16 + 8 * h + g;
                const int c0  = wn + nj * 8 + 2 * t;
                float2 v;
                v.x = acc[mi][nj][2 * h + 0] * 0.125f;
                v.y = acc[mi][nj][2 * h + 1] * 0.125f;
                *reinterpret_cast<float2*>(smem_f + row * RSD + c0) = v;
            }
        }
    }
    __syncthreads();

    // ---- Drain direct tile: out[b, mT*128+r, ncol0+c], coalesced float4 ----
    {
        float* obase = out + ((size_t)bb * SEQ + (size_t)(mT * TILE)) * SEQ
                           + (size_t)ncol0;
        // 128 rows x 16 float4 = 2048 float4 / 256 threads = 8 iters
        #pragma unroll
        for (int i = 0; i < 8; ++i) {
            const int id = i * 256 + tid;
            const int r  = id >> 4;          // 0..127
            const int c4 = id & 15;          // float4 index within 64-col row
            const float4 v = *reinterpret_cast<const float4*>(smem_f + r * RSD + c4 * 4);
            __stcs(reinterpret_cast<float4*>(obase + (size_t)r * SEQ + c4 * 4), v);
        }
    }
}

extern "C" void kernel_launch(void* const* d_in, const int* in_sizes, int n_in,
                              void* d_out, int out_size)
{
    const int*   seq    = (const int*)d_in[0];    // [16, 2048] int32
    const float* weight = (const float*)d_in[1];  // [32000, 64] fp32
    float*       out    = (float*)d_out;          // [16, 2048, 2048] fp32

    (void)in_sizes; (void)n_in; (void)out_size;

    cudaFuncSetAttribute(synergy_kernel,
                         cudaFuncAttributeMaxDynamicSharedMemorySize, SMEM_BYTES);

    dim3 grid(NPAIRS, 2, BATCH);   // (136 pairs, 2 halves, 16 batches)
    synergy_kernel<<<grid, 256, SMEM_BYTES>>>(seq, weight, out);
}

// round 12
// speedup vs baseline: 1.1017x; 1.1017x over previous
#include <cuda_runtime.h>
#include <cuda_fp16.h>
#include <cstdint>

// SynergyGraph: out[b,s,t] = (W[seq[b,s]] . W[seq[b,t]]) / sqrt(64)
// B=16, S=2048, D=64, VOCAB=32000. Output fp32 [16,2048,2048].
//
// fp16 single-pass mma.sync m16n8k16, fp32 accum (rel err ~3e-4).
// Lower-triangle tiles only (Gram symmetry); mirror via SMEM transpose.
// 128x64 CTA tile, 32x32 warp tiles, 4 CTAs/SM.
//
// R12: two-kernel pipeline. Kernel 1 materializes the gathered fp16
// embedding table E[16][2048][64] (4MB __device__ scratch) ONCE -- the
// per-CTA gather previously re-read ~214MB scattered fp32 from L2 and
// re-converted every row ~25x. Kernel 2 = R10 GEMM, but its gather is now
// coalesced 128B fp16 rows from L2-resident E: no seq loads, no convert,
// half the gather bytes. R11's staged direct-store epilogue reverted (it
// regressed); R10 epilogue restored.

#define DEVFN __device__ __forceinline__

static constexpr int BATCH  = 16;
static constexpr int SEQ    = 2048;
static constexpr int TILE   = 128;
static constexpr int NT     = SEQ / TILE;            // 16
static constexpr int NPAIRS = NT * (NT + 1) / 2;     // 136

static constexpr int ROW_BYTES = 144;                // 64 fp16 padded to 72
static constexpr int A_BYTES = 128 * ROW_BYTES;      // 18432
static constexpr int OFF_A = 0;
static constexpr int OFF_B = A_BYTES;
// transpose staging: 64 cols x 128 rows fp32, LDT=132 pad (conflict-free)
static constexpr int LDT = 132;
static constexpr int SMEM_BYTES = 64 * LDT * 4;      // 33792 (> tiles 27648)

// gathered fp16 embeddings: [16][2048][64] = 4MB device scratch
__device__ __align__(16) __half g_emb[BATCH * SEQ * 64];

DEVFN uint32_t smem_u32(const void* p) {
    uint32_t a;
    asm("{ .reg .u64 t; cvta.to.shared.u64 t, %1; cvt.u32.u64 %0, t; }"
        : "=r"(a) : "l"(p));
    return a;
}

DEVFN void sts128(uint32_t addr, uint4 v) {
    asm volatile("st.shared.v4.b32 [%0], {%1, %2, %3, %4};"
                 :: "r"(addr), "r"(v.x), "r"(v.y), "r"(v.z), "r"(v.w) : "memory");
}

DEVFN void ldsm4(uint32_t* r, uint32_t addr) {
    asm volatile("ldmatrix.sync.aligned.m8n8.x4.shared.b16 {%0, %1, %2, %3}, [%4];"
                 : "=r"(r[0]), "=r"(r[1]), "=r"(r[2]), "=r"(r[3]) : "r"(addr));
}

DEVFN void mma16816(float* c, const uint32_t* a, uint32_t b0, uint32_t b1) {
    asm volatile(
        "mma.sync.aligned.m16n8k16.row.col.f32.f16.f16.f32 "
        "{%0, %1, %2, %3}, {%4, %5, %6, %7}, {%8, %9}, {%0, %1, %2, %3};"
        : "+f"(c[0]), "+f"(c[1]), "+f"(c[2]), "+f"(c[3])
        : "r"(a[0]), "r"(a[1]), "r"(a[2]), "r"(a[3]), "r"(b0), "r"(b1));
}

// ---- Kernel 1: gather + fp32->fp16 convert, once per (b,s) row ----
// id = row*16 + chunk; 16 lanes stream one 256B fp32 row -> 128B fp16 row.
__global__ void __launch_bounds__(256)
build_emb_kernel(const int* __restrict__ seq, const float* __restrict__ weight)
{
    const int id    = blockIdx.x * 256 + threadIdx.x;
    const int row   = id >> 4;          // 0..32767 (= b*2048 + s)
    const int chunk = id & 15;          // 16B fp32 chunk

    const int idx = seq[row];
    const float4 v = reinterpret_cast<const float4*>(weight)[(size_t)idx * 16 + chunk];
    const __half2 h0 = __floats2half2_rn(v.x, v.y);
    const __half2 h1 = __floats2half2_rn(v.z, v.w);
    uint2 u;
    u.x = *reinterpret_cast<const uint32_t*>(&h0);
    u.y = *reinterpret_cast<const uint32_t*>(&h1);
    reinterpret_cast<uint2*>(g_emb)[(size_t)row * 16 + chunk] = u;
}

// ---- Kernel 2: symmetric tiled GEMM from E ----
__global__ void __launch_bounds__(256, 4)
synergy_kernel(float* __restrict__ out)
{
    extern __shared__ char smem_raw[];
    const uint32_t smem = smem_u32(smem_raw);
    float* smem_f = reinterpret_cast<float*>(smem_raw);

    const int tid  = threadIdx.x;
    const int wid  = tid >> 5;
    const int lane = tid & 31;

    // ---- pair decode: p -> (mT, nT), mT >= nT; half picks 64-col slice ----
    const int p    = blockIdx.x;
    const int half = blockIdx.y;
    const int bb   = blockIdx.z;
    int mT = (int)((sqrtf(8.0f * (float)p + 1.0f) - 1.0f) * 0.5f);
    while ((mT + 1) * (mT + 2) / 2 <= p) ++mT;
    while (mT * (mT + 1) / 2 > p) --mT;
    const int nT = p - mT * (mT + 1) / 2;
    const int ncol0 = nT * TILE + half * 64;   // output col base of this CTA
    const bool diag = (mT == nT);

    // ---- Coalesced tile load from E (128B fp16 rows) ----
    // id = iter*256 + tid; 8 lanes per row (16B chunks), 4 rows per warp.
    // iters 0..3: A rows (128). iters 4..5: B rows (64) — skipped when diag.
    {
        const int chunk = tid & 7;           // 16B chunk of the 128B fp16 row
        const int rsub  = tid >> 3;          // 0..31
        const uint4* E4 = reinterpret_cast<const uint4*>(g_emb);
        const size_t ebase = (size_t)bb * SEQ;
        const int nIter = diag ? 4 : 6;

        #pragma unroll
        for (int iter = 0; iter < 6; ++iter) {
            if (iter >= nIter) break;
            const int row192 = iter * 32 + rsub;       // 0..191
            const bool isA   = (row192 < 128);
            const int  row   = isA ? row192 : (row192 - 128);
            const int  pos   = isA ? (mT * TILE + row192)
                                   : (ncol0 + row192 - 128);

            const uint4 v = E4[(ebase + pos) * 8 + chunk];

            const uint32_t base = smem + (isA ? OFF_A : OFF_B)
                                + (uint32_t)row * ROW_BYTES + (uint32_t)chunk * 16;
            sts128(base, v);
        }
    }
    __syncthreads();

    // ---- Warp tiling: 8 warps = 4 (M) x 2 (N); warp tile 32x32 ----
    const int wm = (wid >> 1) * 32;   // 0,32,64,96
    const int wn = (wid & 1) * 32;    // 0,32

    float acc[2][4][4];
    #pragma unroll
    for (int mi = 0; mi < 2; ++mi)
        #pragma unroll
        for (int nj = 0; nj < 4; ++nj)
            #pragma unroll
            for (int q = 0; q < 4; ++q) acc[mi][nj][q] = 0.f;

    const int a_row  = lane & 15;
    const int a_col  = (lane >> 4) * 8;
    const int b_row  = (lane & 7) + ((lane >> 4) * 8);
    const int b_col  = ((lane >> 3) & 1) * 8;

    const uint32_t a_base =
        smem + OFF_A + (uint32_t)(wm + a_row) * ROW_BYTES + (uint32_t)a_col * 2;
    // diagonal: B tile aliases rows half*64.. of the A tile
    const uint32_t b_tile = diag ? (smem + OFF_A + (uint32_t)(half * 64) * ROW_BYTES)
                                 : (smem + OFF_B);
    const uint32_t b_base =
        b_tile + (uint32_t)(wn + b_row) * ROW_BYTES + (uint32_t)b_col * 2;

    #pragma unroll
    for (int k = 0; k < 4; ++k) {           // k16 steps over K=64
        const uint32_t koff = (uint32_t)(k * 16) * 2;

        uint32_t bf[2][4];
        #pragma unroll
        for (int bj = 0; bj < 2; ++bj)
            ldsm4(bf[bj], b_base + koff + (uint32_t)(bj * 16) * ROW_BYTES);

        #pragma unroll
        for (int mi = 0; mi < 2; ++mi) {
            uint32_t af[4];
            ldsm4(af, a_base + koff + (uint32_t)(mi * 16) * ROW_BYTES);

            #pragma unroll
            for (int nj = 0; nj < 4; ++nj) {
                const uint32_t* bp = &bf[nj >> 1][(nj & 1) * 2];
                mma16816(acc[mi][nj], af, bp[0], bp[1]);
            }
        }
    }

    const int g = lane >> 2;     // row within 8
    const int t = lane & 3;      // col pair

    // ---- Off-diagonal: stage transposed tile into SMEM (reuses gather smem)
    if (!diag) {
        __syncthreads();   // all ldsm reads of gather smem complete
        // smem_t[c][r]: bank = (4c + r) mod 32 = 8t + g + const -> conflict-free
        #pragma unroll
        for (int mi = 0; mi < 2; ++mi) {
            #pragma unroll
            for (int nj = 0; nj < 4; ++nj) {
                #pragma unroll
                for (int h = 0; h < 2; ++h) {
                    const int row = wm + mi * 16 + 8 * h + g;
                    const int c0  = wn + nj * 8 + 2 * t;
                    smem_f[(c0 + 0) * LDT + row] = acc[mi][nj][2 * h + 0] * 0.125f;
                    smem_f[(c0 + 1) * LDT + row] = acc[mi][nj][2 * h + 1] * 0.125f;
                }
            }
        }
    }

    // ---- Direct tile store (streaming): out[b, mT*128+row, ncol0+col]
    {
        float* obase = out + ((size_t)bb * SEQ + (size_t)(mT * TILE + wm + g)) * SEQ
                           + (size_t)(ncol0 + wn + 2 * t);
        #pragma unroll
        for (int mi = 0; mi < 2; ++mi) {
            #pragma unroll
            for (int h = 0; h < 2; ++h) {
                float* rowp = obase + (size_t)(mi * 16 + 8 * h) * SEQ;
                #pragma unroll
                for (int nj = 0; nj < 4; ++nj) {
                    float2 v;
                    v.x = acc[mi][nj][2 * h + 0] * 0.125f;
                    v.y = acc[mi][nj][2 * h + 1] * 0.125f;
                    __stcs(reinterpret_cast<float2*>(rowp + nj * 8), v);
                }
            }
        }
    }

    // ---- Mirrored tile (streaming): out[b, ncol0+c, mT*128+r] from SMEM
    if (!diag) {
        __syncthreads();
        float* obase = out + ((size_t)bb * SEQ + (size_t)ncol0) * SEQ
                           + (size_t)(mT * TILE);
        // 64 rows x 32 float4 = 2048 float4 / 256 threads = 8 iters
        #pragma unroll
        for (int i = 0; i < 8; ++i) {
            const int id = i * 256 + tid;
            const int r  = id >> 5;          // 0..63: row of mirrored tile
            const int c4 = id & 31;          // float4 index within row
            const float4 v = *reinterpret_cast<const float4*>(smem_f + r * LDT + c4 * 4);
            __stcs(reinterpret_cast<float4*>(obase + (size_t)r * SEQ + c4 * 4), v);
        }
    }
}

extern "C" void kernel_launch(void* const* d_in, const int* in_sizes, int n_in,
                              void* d_out, int out_size)
{
    const int*   seq    = (const int*)d_in[0];    // [16, 2048] int32
    const float* weight = (const float*)d_in[1];  // [32000, 64] fp32
    float*       out    = (float*)d_out;          // [16, 2048, 2048] fp32

    (void)in_sizes; (void)n_in; (void)out_size;

    cudaFuncSetAttribute(synergy_kernel,
                         cudaFuncAttributeMaxDynamicSharedMemorySize, SMEM_BYTES);

    // Kernel 1: materialize fp16 embedding table (16*2048 rows x 16 chunks)
    build_emb_kernel<<<(BATCH * SEQ * 16) / 256, 256>>>(seq, weight);

    // Kernel 2: symmetric GEMM
    dim3 grid(NPAIRS, 2, BATCH);   // (136 pairs, 2 halves, 16 batches)
    synergy_kernel<<<grid, 256, SMEM_BYTES>>>(out);
}